// round 1
// baseline (speedup 1.0000x reference)
#include <cuda_runtime.h>
#include <cuda_bf16.h>
#include <math.h>

// Problem constants
#define BATCH   32
#define NCAPS   1152   // input capsules
#define ILEN    32
#define OCAPS   64     // output capsules
#define OLEN    32

// Scratch (device globals: allocation-free per harness rules)
// P layout: [b][n][o][l]  (row of 32 floats per (b,n,o) = 128B segment)
__device__ float g_P[(size_t)BATCH * NCAPS * OCAPS * OLEN];     // 302 MB
__device__ float g_logits[BATCH * NCAPS * OCAPS];               // [b][n][o]
__device__ float g_probs [BATCH * NCAPS * OCAPS];               // [b][n][o]
__device__ float g_out   [BATCH * OCAPS * OLEN];                // [b][o][l]

// ---------------------------------------------------------------------------
// Kernel 1: priors[b,o,n,l] = sum_i W[o,l,i] * x[b,n,i]
// Block: one (b, 32-n tile). Register-tiled micro-GEMM: each thread owns
// 4n x 8l accumulators for one o; k-loop unrolled by 4 with float4 LDS.
// ---------------------------------------------------------------------------
__global__ __launch_bounds__(256) void k_priors(const float* __restrict__ x,
                                                const float* __restrict__ w) {
    const int b  = blockIdx.y;
    const int n0 = blockIdx.x * 32;
    const int t  = threadIdx.x;

    __shared__ __align__(16) float xs[32][36];          // [n][i], padded
    __shared__ __align__(16) float ws[8][32][36];       // [oc][l][i], padded

    // Load x tile: 32n x 32i = 1024 floats, one float4 per thread
    {
        const int n  = t >> 3;
        const int i0 = (t & 7) * 4;
        float4 v = *(const float4*)&x[((size_t)(b * NCAPS + n0 + n)) * ILEN + i0];
        *(float4*)&xs[n][i0] = v;
    }

    const int tid32 = t & 31;
    const int to = t >> 5;        // o within 8-block
    const int nt = tid32 & 7;     // n base (n = nt + 8j)
    const int lt = tid32 >> 3;    // l group: l = lt*8 .. lt*8+7

    for (int ob = 0; ob < OCAPS; ob += 8) {
        __syncthreads();
        // Load 8 o's worth of W: 8*32*32 floats = 8 float4 per thread
        #pragma unroll
        for (int k = 0; k < 8; k++) {
            const int f  = (t + k * 256) * 4;   // flat float index < 8192
            const int oc = f >> 10;
            const int l  = (f >> 5) & 31;
            const int i0 = f & 28;
            *(float4*)&ws[oc][l][i0] =
                *(const float4*)&w[(size_t)(ob + oc) * (OLEN * ILEN) + (f & 1023)];
        }
        __syncthreads();

        float acc[4][8];
        #pragma unroll
        for (int j = 0; j < 4; j++)
            #pragma unroll
            for (int m = 0; m < 8; m++) acc[j][m] = 0.f;

        #pragma unroll
        for (int k = 0; k < 32; k += 4) {
            float4 xv[4];
            #pragma unroll
            for (int j = 0; j < 4; j++) xv[j] = *(const float4*)&xs[nt + 8 * j][k];
            float4 wv[8];
            #pragma unroll
            for (int m = 0; m < 8; m++) wv[m] = *(const float4*)&ws[to][lt * 8 + m][k];
            #pragma unroll
            for (int j = 0; j < 4; j++)
                #pragma unroll
                for (int m = 0; m < 8; m++)
                    acc[j][m] += xv[j].x * wv[m].x + xv[j].y * wv[m].y +
                                 xv[j].z * wv[m].z + xv[j].w * wv[m].w;
        }

        #pragma unroll
        for (int j = 0; j < 4; j++) {
            const int n = n0 + nt + 8 * j;
            const size_t base =
                ((((size_t)b * NCAPS + n) * OCAPS) + ob + to) * OLEN + lt * 8;
            *(float4*)&g_P[base]     = make_float4(acc[j][0], acc[j][1], acc[j][2], acc[j][3]);
            *(float4*)&g_P[base + 4] = make_float4(acc[j][4], acc[j][5], acc[j][6], acc[j][7]);
        }
    }
}

// ---------------------------------------------------------------------------
// Kernel 2: output[b,o,l] = squash_l( sum_n probs[b,n,o] * P[b,n,o,l] )
// Block per (b,o). 8 threads per P-row (fully coalesced 128B segments).
// ---------------------------------------------------------------------------
template <bool UNIFORM>
__global__ __launch_bounds__(256) void k_out(float* __restrict__ dst) {
    const int b = blockIdx.y;
    const int o = blockIdx.x;
    const int t = threadIdx.x;
    const int sub = t & 7;    // which float4 of the 32-float row
    const int ng  = t >> 3;   // 0..31: n stride group

    float4 acc = make_float4(0.f, 0.f, 0.f, 0.f);
    for (int n = ng; n < NCAPS; n += 32) {
        const float p = UNIFORM ? (1.0f / OCAPS)
                                : g_probs[((size_t)b * NCAPS + n) * OCAPS + o];
        const float4 v = *(const float4*)
            &g_P[((((size_t)b * NCAPS + n) * OCAPS) + o) * OLEN + sub * 4];
        acc.x += p * v.x; acc.y += p * v.y; acc.z += p * v.z; acc.w += p * v.w;
    }

    __shared__ float4 red[256];
    red[t] = acc;
    __syncthreads();
    if (t < 64) {
        float4 a = red[t], c = red[t + 64], d = red[t + 128], e = red[t + 192];
        a.x += c.x + d.x + e.x; a.y += c.y + d.y + e.y;
        a.z += c.z + d.z + e.z; a.w += c.w + d.w + e.w;
        red[t] = a;
    }
    __syncthreads();
    if (t < 8) {
        float4 a = red[t];
        #pragma unroll
        for (int g = 1; g < 8; g++) {
            float4 e = red[t + 8 * g];
            a.x += e.x; a.y += e.y; a.z += e.z; a.w += e.w;
        }
        float ss = a.x * a.x + a.y * a.y + a.z * a.z + a.w * a.w;
        #pragma unroll
        for (int off = 4; off; off >>= 1) ss += __shfl_xor_sync(0xff, ss, off);
        const float scale = sqrtf(ss) / (1.0f + ss);   // ||v||/(1+||v||^2)
        a.x *= scale; a.y *= scale; a.z *= scale; a.w *= scale;
        const size_t base = ((size_t)b * OCAPS + o) * OLEN + t * 4;
        *(float4*)&g_out[base] = a;
        if (dst) *(float4*)&dst[base] = a;
    }
}

// ---------------------------------------------------------------------------
// Kernel 3 (fused): logits[b,n,o] += dot_l(P[b,n,o,:], out[b,o,:]);
//                   probs[b,n,:]   = softmax_o(logits[b,n,:])
// Block per (b, 8-n tile); one warp per n; lane handles o=lane and o=lane+32.
// ---------------------------------------------------------------------------
template <bool FIRST>
__global__ __launch_bounds__(256) void k_agree() {
    const int b  = blockIdx.y;
    const int n0 = blockIdx.x * 8;
    const int t  = threadIdx.x;
    const int wrp  = t >> 5;
    const int lane = t & 31;

    __shared__ __align__(16) float outS[OCAPS * OLEN];   // 8 KB
    for (int idx = t; idx < OCAPS * OLEN; idx += 256)
        outS[idx] = g_out[(size_t)b * OCAPS * OLEN + idx];
    __syncthreads();

    const int n = n0 + wrp;
    float vals[2];
    #pragma unroll
    for (int h = 0; h < 2; h++) {
        const int o = lane + h * 32;
        const float4* pr = (const float4*)
            &g_P[((((size_t)b * NCAPS + n) * OCAPS) + o) * OLEN];
        const float4* os = (const float4*)&outS[o * OLEN];
        float d = 0.f;
        #pragma unroll
        for (int m = 0; m < 8; m++) {
            const float4 pv = pr[m];
            const float4 ov = os[m];
            d += pv.x * ov.x + pv.y * ov.y + pv.z * ov.z + pv.w * ov.w;
        }
        const size_t li = ((size_t)b * NCAPS + n) * OCAPS + o;
        const float nl = FIRST ? d : (g_logits[li] + d);
        g_logits[li] = nl;
        vals[h] = nl;
    }

    // softmax over the 64 o-values held by this warp (2 per lane)
    float mx = fmaxf(vals[0], vals[1]);
    #pragma unroll
    for (int off = 16; off; off >>= 1)
        mx = fmaxf(mx, __shfl_xor_sync(0xffffffffu, mx, off));
    const float e0 = __expf(vals[0] - mx);
    const float e1 = __expf(vals[1] - mx);
    float s = e0 + e1;
    #pragma unroll
    for (int off = 16; off; off >>= 1)
        s += __shfl_xor_sync(0xffffffffu, s, off);
    const float inv = 1.0f / s;
    const size_t li0 = ((size_t)b * NCAPS + n) * OCAPS;
    g_probs[li0 + lane]      = e0 * inv;
    g_probs[li0 + lane + 32] = e1 * inv;
}

// ---------------------------------------------------------------------------
extern "C" void kernel_launch(void* const* d_in, const int* in_sizes, int n_in,
                              void* d_out, int out_size) {
    const float* x = (const float*)d_in[0];   // [32,1152,32]
    const float* w = (const float*)d_in[1];   // [64,32,32]
    float* out = (float*)d_out;               // [32,64,32]

    k_priors<<<dim3(NCAPS / 32, BATCH), 256>>>(x, w);

    // iteration 0: logits = 0 -> probs uniform (analytic)
    k_out<true><<<dim3(OCAPS, BATCH), 256>>>(nullptr);
    k_agree<true><<<dim3(NCAPS / 8, BATCH), 256>>>();

    // iteration 1
    k_out<false><<<dim3(OCAPS, BATCH), 256>>>(nullptr);
    k_agree<false><<<dim3(NCAPS / 8, BATCH), 256>>>();

    // iteration 2 (final): write d_out
    k_out<false><<<dim3(OCAPS, BATCH), 256>>>(out);
}

// round 2
// speedup vs baseline: 4.4451x; 4.4451x over previous
#include <cuda_runtime.h>
#include <cuda_bf16.h>
#include <math.h>

#define BATCH   32
#define NCAPS   1152
#define ILEN    32
#define OCAPS   64
#define OLEN    32
#define NCHUNK  8
#define CHLEN   (NCAPS / NCHUNK)   // 144

// Small scratch only — priors are never materialized.
__device__ float g_sx    [BATCH * ILEN];                        // col-sum of x
__device__ float g_spart [NCHUNK * BATCH * OCAPS * ILEN];       // partial s (2 MB)
__device__ float g_t     [BATCH * OCAPS * ILEN];                // W^T · out
__device__ float g_logits[BATCH * NCAPS * OCAPS];               // 9.4 MB
__device__ float g_probs [BATCH * NCAPS * OCAPS];               // 9.4 MB

// ---------------------------------------------------------------------------
// sx[b,i] = sum_n x[b,n,i]   (for iteration 0's uniform coupling)
// ---------------------------------------------------------------------------
__global__ __launch_bounds__(256) void k_colsum(const float* __restrict__ x) {
    const int b = blockIdx.x;
    const int i = threadIdx.x & 31;
    const int g = threadIdx.x >> 5;
    float acc = 0.f;
    for (int n = g; n < NCAPS; n += 8)
        acc += x[((size_t)b * NCAPS + n) * ILEN + i];
    __shared__ float red[8][32];
    red[g][i] = acc;
    __syncthreads();
    if (threadIdx.x < 32) {
        float s = 0.f;
        #pragma unroll
        for (int k = 0; k < 8; k++) s += red[k][i];
        g_sx[b * ILEN + i] = s;
    }
}

// ---------------------------------------------------------------------------
// s[b,o,i] partials: s += sum_{n in chunk} probs[b,n,o] * x[b,n,i]
// grid (NCHUNK, BATCH), 128 threads; each thread owns a 4o x 4i register tile.
// ---------------------------------------------------------------------------
__global__ __launch_bounds__(128) void k_s(const float* __restrict__ x) {
    const int c = blockIdx.x;
    const int b = blockIdx.y;
    const int t = threadIdx.x;
    const int o4 = (t & 15) * 4;
    const int i4 = (t >> 4) * 4;

    float acc[4][4];
    #pragma unroll
    for (int m = 0; m < 4; m++)
        #pragma unroll
        for (int j = 0; j < 4; j++) acc[m][j] = 0.f;

    const int n0 = c * CHLEN;
    #pragma unroll 4
    for (int n = n0; n < n0 + CHLEN; n++) {
        const float4 pv = *(const float4*)&g_probs[((size_t)b * NCAPS + n) * OCAPS + o4];
        const float4 xv = *(const float4*)&x[((size_t)b * NCAPS + n) * ILEN + i4];
        const float p[4] = {pv.x, pv.y, pv.z, pv.w};
        const float xr[4] = {xv.x, xv.y, xv.z, xv.w};
        #pragma unroll
        for (int m = 0; m < 4; m++)
            #pragma unroll
            for (int j = 0; j < 4; j++) acc[m][j] += p[m] * xr[j];
    }

    #pragma unroll
    for (int m = 0; m < 4; m++)
        *(float4*)&g_spart[(((size_t)c * BATCH + b) * OCAPS + o4 + m) * ILEN + i4] =
            make_float4(acc[m][0], acc[m][1], acc[m][2], acc[m][3]);
}

// ---------------------------------------------------------------------------
// out[b,o,l] = squash_l( W[o,l,:] . s[b,o,:] );  t[b,o,i] = sum_l W[o,l,i]*out[l]
// grid (16, BATCH), 128 threads = 4 warps, one warp per o.
// ---------------------------------------------------------------------------
template <bool UNIFORM, bool FINAL>
__global__ __launch_bounds__(128) void k_outT(const float* __restrict__ w,
                                              float* __restrict__ dst) {
    const int b = blockIdx.y;
    const int o = blockIdx.x * 4 + (threadIdx.x >> 5);
    const int lane = threadIdx.x & 31;

    // s[i = lane]
    float s_l;
    if (UNIFORM) {
        s_l = g_sx[b * ILEN + lane] * (1.0f / OCAPS);
    } else {
        s_l = 0.f;
        #pragma unroll
        for (int c = 0; c < NCHUNK; c++)
            s_l += g_spart[(((size_t)c * BATCH + b) * OCAPS + o) * ILEN + lane];
    }

    // W[o][lane][:] into registers
    float wrow[32];
    {
        const float4* wp = (const float4*)&w[((size_t)o * OLEN + lane) * ILEN];
        #pragma unroll
        for (int m = 0; m < 8; m++) {
            const float4 v = wp[m];
            wrow[m * 4 + 0] = v.x; wrow[m * 4 + 1] = v.y;
            wrow[m * 4 + 2] = v.z; wrow[m * 4 + 3] = v.w;
        }
    }

    // out[l = lane] = sum_i W[o][lane][i] * s[i]
    float out_l = 0.f;
    #pragma unroll
    for (int i = 0; i < 32; i++)
        out_l += wrow[i] * __shfl_sync(0xffffffffu, s_l, i);

    // squash
    float ss = out_l * out_l;
    #pragma unroll
    for (int off = 16; off; off >>= 1) ss += __shfl_xor_sync(0xffffffffu, ss, off);
    const float scale = sqrtf(ss) / (1.0f + ss);
    out_l *= scale;

    if (FINAL) {
        dst[((size_t)b * OCAPS + o) * OLEN + lane] = out_l;
    } else {
        // t[i = lane] = sum_l W[o][l][lane] * out[l]
        float t_l = 0.f;
        #pragma unroll
        for (int l = 0; l < 32; l++)
            t_l += w[((size_t)o * OLEN + l) * ILEN + lane] *
                   __shfl_sync(0xffffffffu, out_l, l);
        g_t[((size_t)b * OCAPS + o) * ILEN + lane] = t_l;
    }
}

// ---------------------------------------------------------------------------
// logits[b,n,o] += x[b,n,:] . t[b,o,:];  probs[b,n,:] = softmax_o(logits)
// grid (NCAPS/32, BATCH), 256 threads = 8 warps, 4 n per warp.
// Lane holds t rows for o = lane and o = lane+32 in registers.
// ---------------------------------------------------------------------------
template <bool FIRST, bool STORE_LOGITS>
__global__ __launch_bounds__(256) void k_agree(const float* __restrict__ x) {
    const int b = blockIdx.y;
    const int n0 = blockIdx.x * 32;
    const int wrp = threadIdx.x >> 5;
    const int lane = threadIdx.x & 31;

    float t0[32], t1[32];
    {
        const float4* tp0 = (const float4*)&g_t[((size_t)b * OCAPS + lane) * ILEN];
        const float4* tp1 = (const float4*)&g_t[((size_t)b * OCAPS + lane + 32) * ILEN];
        #pragma unroll
        for (int m = 0; m < 8; m++) {
            float4 v = tp0[m];
            t0[m * 4 + 0] = v.x; t0[m * 4 + 1] = v.y; t0[m * 4 + 2] = v.z; t0[m * 4 + 3] = v.w;
            v = tp1[m];
            t1[m * 4 + 0] = v.x; t1[m * 4 + 1] = v.y; t1[m * 4 + 2] = v.z; t1[m * 4 + 3] = v.w;
        }
    }

    #pragma unroll
    for (int k = 0; k < 4; k++) {
        const int n = n0 + wrp * 4 + k;
        const float xv = x[((size_t)b * NCAPS + n) * ILEN + lane];
        float d0 = 0.f, d1 = 0.f;
        #pragma unroll
        for (int i = 0; i < 32; i++) {
            const float xi = __shfl_sync(0xffffffffu, xv, i);
            d0 += t0[i] * xi;
            d1 += t1[i] * xi;
        }
        const size_t li = ((size_t)b * NCAPS + n) * OCAPS;
        const float nl0 = FIRST ? d0 : (g_logits[li + lane] + d0);
        const float nl1 = FIRST ? d1 : (g_logits[li + lane + 32] + d1);
        if (STORE_LOGITS) {
            g_logits[li + lane] = nl0;
            g_logits[li + lane + 32] = nl1;
        }
        // softmax over the 64 o-values (2 per lane)
        float mx = fmaxf(nl0, nl1);
        #pragma unroll
        for (int off = 16; off; off >>= 1)
            mx = fmaxf(mx, __shfl_xor_sync(0xffffffffu, mx, off));
        const float e0 = __expf(nl0 - mx);
        const float e1 = __expf(nl1 - mx);
        float s = e0 + e1;
        #pragma unroll
        for (int off = 16; off; off >>= 1)
            s += __shfl_xor_sync(0xffffffffu, s, off);
        const float inv = 1.0f / s;
        g_probs[li + lane] = e0 * inv;
        g_probs[li + lane + 32] = e1 * inv;
    }
}

// ---------------------------------------------------------------------------
extern "C" void kernel_launch(void* const* d_in, const int* in_sizes, int n_in,
                              void* d_out, int out_size) {
    const float* x = (const float*)d_in[0];   // [32,1152,32]
    const float* w = (const float*)d_in[1];   // [64,32,32]
    float* out = (float*)d_out;               // [32,64,32]

    // iteration 0: probs uniform -> s = colsum(x)/64
    k_colsum<<<BATCH, 256>>>(x);
    k_outT<true, false><<<dim3(16, BATCH), 128>>>(w, nullptr);
    k_agree<true, true><<<dim3(NCAPS / 32, BATCH), 256>>>(x);

    // iteration 1
    k_s<<<dim3(NCHUNK, BATCH), 128>>>(x);
    k_outT<false, false><<<dim3(16, BATCH), 128>>>(w, nullptr);
    k_agree<false, false><<<dim3(NCAPS / 32, BATCH), 256>>>(x);

    // iteration 2 (final)
    k_s<<<dim3(NCHUNK, BATCH), 128>>>(x);
    k_outT<false, true><<<dim3(16, BATCH), 128>>>(w, out);
}

// round 3
// speedup vs baseline: 7.3533x; 1.6543x over previous
#include <cuda_runtime.h>
#include <cuda_bf16.h>
#include <math.h>

#define BATCH   32
#define NCAPS   1152
#define ILEN    32
#define OCAPS   64
#define OLEN    32
#define NCHUNK  36
#define CHLEN   32            // n's per fused block

// Scratch — no priors, no probs, no logits in gmem.
__device__ float g_sx   [BATCH * ILEN];                    // col-sum of x
__device__ float g_spart[NCHUNK * BATCH * OCAPS * ILEN];   // partial s (9.4 MB)
__device__ float g_tcum [BATCH * OCAPS * ILEN];            // cumulative W^T·out

// ---------------------------------------------------------------------------
// sx[b,i] = sum_n x[b,n,i]   (iteration 0's uniform coupling)
// ---------------------------------------------------------------------------
__global__ __launch_bounds__(256) void k_colsum(const float* __restrict__ x) {
    const int b = blockIdx.x;
    const int i = threadIdx.x & 31;
    const int g = threadIdx.x >> 5;
    float acc = 0.f;
    #pragma unroll 4
    for (int n = g; n < NCAPS; n += 8)
        acc += x[((size_t)b * NCAPS + n) * ILEN + i];
    __shared__ float red[8][32];
    red[g][i] = acc;
    __syncthreads();
    if (threadIdx.x < 32) {
        float s = 0.f;
        #pragma unroll
        for (int k = 0; k < 8; k++) s += red[k][i];
        g_sx[b * ILEN + i] = s;
    }
}

// ---------------------------------------------------------------------------
// Fused routing step for a 32-n tile of batch b:
//   logits[n,o] = x[n,:]·t_cum[o,:]   (recomputed, never stored)
//   probs[n,:]  = softmax_o(logits)   (SMEM only)
//   spart[c,b,o,i] = sum_{n in tile} probs[n,o]·x[n,i]
// grid (NCHUNK, BATCH), 256 threads.
// ---------------------------------------------------------------------------
__global__ __launch_bounds__(256) void k_fused(const float* __restrict__ x) {
    const int c = blockIdx.x;
    const int b = blockIdx.y;
    const int t = threadIdx.x;
    const int lane = t & 31;
    const int w = t >> 5;

    __shared__ __align__(16) float xs[32][32];   // 4 KB
    __shared__ __align__(16) float ps[32][64];   // 8 KB

    // load x tile (one float4/thread)
    {
        const int n = t >> 3, i4 = (t & 7) * 4;
        *(float4*)&xs[n][i4] =
            *(const float4*)&x[((size_t)b * NCAPS + c * CHLEN + n) * ILEN + i4];
    }

    // t_cum rows for o=lane and o=lane+32 into registers
    float t0[32], t1[32];
    {
        const float4* tp0 = (const float4*)&g_tcum[((size_t)b * OCAPS + lane) * ILEN];
        const float4* tp1 = (const float4*)&g_tcum[((size_t)b * OCAPS + lane + 32) * ILEN];
        #pragma unroll
        for (int m = 0; m < 8; m++) {
            float4 v = tp0[m];
            t0[m*4+0]=v.x; t0[m*4+1]=v.y; t0[m*4+2]=v.z; t0[m*4+3]=v.w;
            v = tp1[m];
            t1[m*4+0]=v.x; t1[m*4+1]=v.y; t1[m*4+2]=v.z; t1[m*4+3]=v.w;
        }
    }
    __syncthreads();

    // Phase 1: logits + softmax, 4 n per warp
    #pragma unroll
    for (int k = 0; k < 4; k++) {
        const int n = w * 4 + k;
        float d0 = 0.f, d1 = 0.f;
        #pragma unroll
        for (int m = 0; m < 8; m++) {
            const float4 xv = *(const float4*)&xs[n][m * 4];   // broadcast LDS
            d0 += t0[m*4]*xv.x + t0[m*4+1]*xv.y + t0[m*4+2]*xv.z + t0[m*4+3]*xv.w;
            d1 += t1[m*4]*xv.x + t1[m*4+1]*xv.y + t1[m*4+2]*xv.z + t1[m*4+3]*xv.w;
        }
        float mx = fmaxf(d0, d1);
        #pragma unroll
        for (int off = 16; off; off >>= 1)
            mx = fmaxf(mx, __shfl_xor_sync(0xffffffffu, mx, off));
        const float e0 = __expf(d0 - mx);
        const float e1 = __expf(d1 - mx);
        float s = e0 + e1;
        #pragma unroll
        for (int off = 16; off; off >>= 1)
            s += __shfl_xor_sync(0xffffffffu, s, off);
        const float inv = 1.0f / s;
        ps[n][lane]      = e0 * inv;
        ps[n][lane + 32] = e1 * inv;
    }
    __syncthreads();

    // Phase 2: partial s[o,i] = sum_n ps[n][o] * xs[n][i]
    // thread: i = lane, o-group = warp (8 o's)
    float acc[8];
    #pragma unroll
    for (int j = 0; j < 8; j++) acc[j] = 0.f;
    #pragma unroll 8
    for (int n = 0; n < 32; n++) {
        const float xv = xs[n][lane];                         // conflict-free
        const float4 p0 = *(const float4*)&ps[n][w * 8];      // broadcast
        const float4 p1 = *(const float4*)&ps[n][w * 8 + 4];
        acc[0] += p0.x * xv; acc[1] += p0.y * xv;
        acc[2] += p0.z * xv; acc[3] += p0.w * xv;
        acc[4] += p1.x * xv; acc[5] += p1.y * xv;
        acc[6] += p1.z * xv; acc[7] += p1.w * xv;
    }
    #pragma unroll
    for (int j = 0; j < 8; j++)
        g_spart[(((size_t)c * BATCH + b) * OCAPS + w * 8 + j) * ILEN + lane] = acc[j];
}

// ---------------------------------------------------------------------------
// out[b,o,l] = squash_l( W[o,l,:]·s[b,o,:] );  t_cum[b,o,i] += W^T·out
// grid (16, BATCH), 128 threads = 4 warps, one warp per o.
// ---------------------------------------------------------------------------
template <bool UNIFORM, bool FINAL>
__global__ __launch_bounds__(128) void k_outT(const float* __restrict__ w,
                                              float* __restrict__ dst) {
    const int b = blockIdx.y;
    const int o = blockIdx.x * 4 + (threadIdx.x >> 5);
    const int lane = threadIdx.x & 31;

    // s[i = lane]
    float s_l;
    if (UNIFORM) {
        s_l = g_sx[b * ILEN + lane] * (1.0f / OCAPS);
    } else {
        s_l = 0.f;
        #pragma unroll
        for (int c = 0; c < NCHUNK; c++)
            s_l += g_spart[(((size_t)c * BATCH + b) * OCAPS + o) * ILEN + lane];
    }

    // W[o][lane][:] into registers
    float wrow[32];
    {
        const float4* wp = (const float4*)&w[((size_t)o * OLEN + lane) * ILEN];
        #pragma unroll
        for (int m = 0; m < 8; m++) {
            const float4 v = wp[m];
            wrow[m*4+0]=v.x; wrow[m*4+1]=v.y; wrow[m*4+2]=v.z; wrow[m*4+3]=v.w;
        }
    }

    // out[l = lane] = sum_i W[o][lane][i] * s[i]
    float out_l = 0.f;
    #pragma unroll
    for (int i = 0; i < 32; i++)
        out_l += wrow[i] * __shfl_sync(0xffffffffu, s_l, i);

    // squash
    float ss = out_l * out_l;
    #pragma unroll
    for (int off = 16; off; off >>= 1) ss += __shfl_xor_sync(0xffffffffu, ss, off);
    const float scale = sqrtf(ss) / (1.0f + ss);
    out_l *= scale;

    if (FINAL) {
        dst[((size_t)b * OCAPS + o) * OLEN + lane] = out_l;
    } else {
        // t[i = lane] = sum_l W[o][l][lane] * out[l]; accumulate into t_cum
        float t_l = 0.f;
        #pragma unroll
        for (int l = 0; l < 32; l++)
            t_l += w[((size_t)o * OLEN + l) * ILEN + lane] *
                   __shfl_sync(0xffffffffu, out_l, l);
        const size_t ti = ((size_t)b * OCAPS + o) * ILEN + lane;
        g_tcum[ti] = UNIFORM ? t_l : (g_tcum[ti] + t_l);
    }
}

// ---------------------------------------------------------------------------
extern "C" void kernel_launch(void* const* d_in, const int* in_sizes, int n_in,
                              void* d_out, int out_size) {
    const float* x = (const float*)d_in[0];   // [32,1152,32]
    const float* w = (const float*)d_in[1];   // [64,32,32]
    float* out = (float*)d_out;               // [32,64,32]

    // iteration 0: uniform coupling
    k_colsum<<<BATCH, 256>>>(x);
    k_outT<true, false><<<dim3(16, BATCH), 128>>>(w, nullptr);

    // iteration 1
    k_fused<<<dim3(NCHUNK, BATCH), 256>>>(x);
    k_outT<false, false><<<dim3(16, BATCH), 128>>>(w, nullptr);

    // iteration 2 (final)
    k_fused<<<dim3(NCHUNK, BATCH), 256>>>(x);
    k_outT<false, true><<<dim3(16, BATCH), 128>>>(w, out);
}

// round 4
// speedup vs baseline: 10.5189x; 1.4305x over previous
#include <cuda_runtime.h>
#include <cuda_bf16.h>
#include <math.h>

#define BATCH   32
#define NCAPS   1152
#define ILEN    32
#define OCAPS   64
#define OLEN    32
#define CHLEN   64                 // n's per fused block
#define NCHUNK  (NCAPS / CHLEN)    // 18
#define CSCH    8                  // colsum chunks

// Scratch — no priors, no probs, no logits in gmem.
__device__ float g_sxp  [CSCH * BATCH * ILEN];             // colsum partials
__device__ float g_spart[NCHUNK * BATCH * OCAPS * ILEN];   // partial s (4.7 MB)
__device__ float g_tcum [BATCH * OCAPS * ILEN];            // cumulative W^T·out

// ---------------------------------------------------------------------------
// sxp[c,b,i] = sum_{n in chunk c} x[b,n,i]
// ---------------------------------------------------------------------------
__global__ __launch_bounds__(256) void k_colsum(const float* __restrict__ x) {
    const int c = blockIdx.x;
    const int b = blockIdx.y;
    const int i = threadIdx.x & 31;
    const int g = threadIdx.x >> 5;
    const int n0 = c * (NCAPS / CSCH);   // 144 rows per chunk
    float acc = 0.f;
    #pragma unroll 6
    for (int n = n0 + g; n < n0 + NCAPS / CSCH; n += 8)
        acc += x[((size_t)b * NCAPS + n) * ILEN + i];
    __shared__ float red[8][32];
    red[g][i] = acc;
    __syncthreads();
    if (threadIdx.x < 32) {
        float s = 0.f;
        #pragma unroll
        for (int k = 0; k < 8; k++) s += red[k][i];
        g_sxp[(c * BATCH + b) * ILEN + i] = s;
    }
}

// ---------------------------------------------------------------------------
// Fused routing step for a 64-n tile of batch b:
//   logits[n,o] = x[n,:]·t_cum[o,:]  ->  probs = softmax_o  (SMEM only)
//   spart[c,b,o,i] = sum_{n in tile} probs[n,o]·x[n,i]
// grid (NCHUNK, BATCH), 256 threads (8 warps, 8 n each in phase 1).
// ---------------------------------------------------------------------------
__global__ __launch_bounds__(256) void k_fused(const float* __restrict__ x) {
    const int c = blockIdx.x;
    const int b = blockIdx.y;
    const int t = threadIdx.x;
    const int lane = t & 31;
    const int w = t >> 5;

    __shared__ __align__(16) float xs[CHLEN][32];     // 8 KB
    __shared__ __align__(16) float ps[CHLEN][64];     // 16 KB

    // load x tile (two float4 per thread)
    {
        const float4* src = (const float4*)&x[((size_t)b * NCAPS + c * CHLEN) * ILEN];
        ((float4*)xs)[t]       = src[t];
        ((float4*)xs)[t + 256] = src[t + 256];
    }

    // t_cum rows for o=lane, o=lane+32 into registers
    float t0[32], t1[32];
    {
        const float4* tp0 = (const float4*)&g_tcum[((size_t)b * OCAPS + lane) * ILEN];
        const float4* tp1 = (const float4*)&g_tcum[((size_t)b * OCAPS + lane + 32) * ILEN];
        #pragma unroll
        for (int m = 0; m < 8; m++) {
            float4 v = tp0[m];
            t0[m*4+0]=v.x; t0[m*4+1]=v.y; t0[m*4+2]=v.z; t0[m*4+3]=v.w;
            v = tp1[m];
            t1[m*4+0]=v.x; t1[m*4+1]=v.y; t1[m*4+2]=v.z; t1[m*4+3]=v.w;
        }
    }
    __syncthreads();

    // Phase 1: logits + softmax, 8 n per warp, processed in pairs for ILP
    #pragma unroll
    for (int k = 0; k < 8; k += 2) {
        const int na = w * 8 + k;
        const int nb = na + 1;
        float a0 = 0.f, a1 = 0.f, b0 = 0.f, b1 = 0.f;
        #pragma unroll
        for (int m = 0; m < 8; m++) {
            const float4 xa = *(const float4*)&xs[na][m * 4];
            const float4 xb = *(const float4*)&xs[nb][m * 4];
            a0 += t0[m*4]*xa.x + t0[m*4+1]*xa.y + t0[m*4+2]*xa.z + t0[m*4+3]*xa.w;
            a1 += t1[m*4]*xa.x + t1[m*4+1]*xa.y + t1[m*4+2]*xa.z + t1[m*4+3]*xa.w;
            b0 += t0[m*4]*xb.x + t0[m*4+1]*xb.y + t0[m*4+2]*xb.z + t0[m*4+3]*xb.w;
            b1 += t1[m*4]*xb.x + t1[m*4+1]*xb.y + t1[m*4+2]*xb.z + t1[m*4+3]*xb.w;
        }
        float mxa = fmaxf(a0, a1), mxb = fmaxf(b0, b1);
        #pragma unroll
        for (int off = 16; off; off >>= 1) {
            mxa = fmaxf(mxa, __shfl_xor_sync(0xffffffffu, mxa, off));
            mxb = fmaxf(mxb, __shfl_xor_sync(0xffffffffu, mxb, off));
        }
        const float ea0 = __expf(a0 - mxa), ea1 = __expf(a1 - mxa);
        const float eb0 = __expf(b0 - mxb), eb1 = __expf(b1 - mxb);
        float sa = ea0 + ea1, sb = eb0 + eb1;
        #pragma unroll
        for (int off = 16; off; off >>= 1) {
            sa += __shfl_xor_sync(0xffffffffu, sa, off);
            sb += __shfl_xor_sync(0xffffffffu, sb, off);
        }
        const float ia = 1.0f / sa, ib = 1.0f / sb;
        ps[na][lane]      = ea0 * ia;
        ps[na][lane + 32] = ea1 * ia;
        ps[nb][lane]      = eb0 * ib;
        ps[nb][lane + 32] = eb1 * ib;
    }
    __syncthreads();

    // Phase 2: partial s[o,i] = sum_n ps[n][o] * xs[n][i]
    // thread: i = lane, warp owns 8 o's
    float acc[8];
    #pragma unroll
    for (int j = 0; j < 8; j++) acc[j] = 0.f;
    #pragma unroll 8
    for (int n = 0; n < CHLEN; n++) {
        const float xv = xs[n][lane];                       // conflict-free
        const float4 p0 = *(const float4*)&ps[n][w * 8];    // broadcast
        const float4 p1 = *(const float4*)&ps[n][w * 8 + 4];
        acc[0] += p0.x * xv; acc[1] += p0.y * xv;
        acc[2] += p0.z * xv; acc[3] += p0.w * xv;
        acc[4] += p1.x * xv; acc[5] += p1.y * xv;
        acc[6] += p1.z * xv; acc[7] += p1.w * xv;
    }
    #pragma unroll
    for (int j = 0; j < 8; j++)
        g_spart[(((size_t)c * BATCH + b) * OCAPS + w * 8 + j) * ILEN + lane] = acc[j];
}

// ---------------------------------------------------------------------------
// out[b,o,l] = squash_l( W[o,l,:]·s[b,o,:] );  t_cum[b,o,i] += W^T·out
// grid (16, BATCH), 128 threads = 4 warps, one warp per o.
// ---------------------------------------------------------------------------
template <bool UNIFORM, bool FINAL>
__global__ __launch_bounds__(128) void k_outT(const float* __restrict__ w,
                                              float* __restrict__ dst) {
    const int b = blockIdx.y;
    const int o = blockIdx.x * 4 + (threadIdx.x >> 5);
    const int lane = threadIdx.x & 31;

    // s[i = lane]
    float s_l = 0.f;
    if (UNIFORM) {
        #pragma unroll
        for (int c = 0; c < CSCH; c++)
            s_l += g_sxp[(c * BATCH + b) * ILEN + lane];
        s_l *= (1.0f / OCAPS);
    } else {
        #pragma unroll
        for (int c = 0; c < NCHUNK; c++)
            s_l += g_spart[(((size_t)c * BATCH + b) * OCAPS + o) * ILEN + lane];
    }

    // W[o][lane][:] into registers
    float wrow[32];
    {
        const float4* wp = (const float4*)&w[((size_t)o * OLEN + lane) * ILEN];
        #pragma unroll
        for (int m = 0; m < 8; m++) {
            const float4 v = wp[m];
            wrow[m*4+0]=v.x; wrow[m*4+1]=v.y; wrow[m*4+2]=v.z; wrow[m*4+3]=v.w;
        }
    }

    // out[l = lane] = sum_i W[o][lane][i] * s[i]
    float out_l = 0.f;
    #pragma unroll
    for (int i = 0; i < 32; i++)
        out_l += wrow[i] * __shfl_sync(0xffffffffu, s_l, i);

    // squash
    float ss = out_l * out_l;
    #pragma unroll
    for (int off = 16; off; off >>= 1) ss += __shfl_xor_sync(0xffffffffu, ss, off);
    const float scale = sqrtf(ss) / (1.0f + ss);
    out_l *= scale;

    if (FINAL) {
        dst[((size_t)b * OCAPS + o) * OLEN + lane] = out_l;
    } else {
        // t[i = lane] = sum_l W[o][l][lane] * out[l]; accumulate into t_cum
        float t_l = 0.f;
        #pragma unroll
        for (int l = 0; l < 32; l++)
            t_l += w[((size_t)o * OLEN + l) * ILEN + lane] *
                   __shfl_sync(0xffffffffu, out_l, l);
        const size_t ti = ((size_t)b * OCAPS + o) * ILEN + lane;
        g_tcum[ti] = UNIFORM ? t_l : (g_tcum[ti] + t_l);
    }
}

// ---------------------------------------------------------------------------
extern "C" void kernel_launch(void* const* d_in, const int* in_sizes, int n_in,
                              void* d_out, int out_size) {
    const float* x = (const float*)d_in[0];   // [32,1152,32]
    const float* w = (const float*)d_in[1];   // [64,32,32]
    float* out = (float*)d_out;               // [32,64,32]

    // iteration 0: uniform coupling
    k_colsum<<<dim3(CSCH, BATCH), 256>>>(x);
    k_outT<true, false><<<dim3(16, BATCH), 128>>>(w, nullptr);

    // iteration 1
    k_fused<<<dim3(NCHUNK, BATCH), 256>>>(x);
    k_outT<false, false><<<dim3(16, BATCH), 128>>>(w, nullptr);

    // iteration 2 (final)
    k_fused<<<dim3(NCHUNK, BATCH), 256>>>(x);
    k_outT<false, true><<<dim3(16, BATCH), 128>>>(w, out);
}

// round 7
// speedup vs baseline: 15.7052x; 1.4931x over previous
#include <cuda_runtime.h>
#include <cuda_bf16.h>
#include <cstdint>
#include <stdint.h>
#include <math.h>

#define BATCH   32
#define NCAPS   1152
#define ILEN    32
#define OCAPS   64
#define OLEN    32
#define CLU     4                  // CTAs per cluster (one cluster per batch)
#define NPC     (NCAPS / CLU)      // 288 input caps per CTA
#define OPC     (OCAPS / CLU)      // 16 output caps per CTA
#define TPB     512
#define NWARP   16
#define NPW     (NPC / NWARP)      // 18 n per warp in phase 1

// SMEM layout (float offsets)
#define XS_OFF  0                          // [288][32]        9216
#define PS_OFF  (XS_OFF + NPC * ILEN)      // [288][64]       18432
#define TS_OFF  (PS_OFF + NPC * OCAPS)     // [64][33] padded  2112
#define SP_OFF  (TS_OFF + OCAPS * 33)      // [4][16][32]      2048
#define SX_OFF  (SP_OFF + CLU * OPC * 32)  // [4][32]           128
#define SM_FLOATS (SX_OFF + CLU * 32)
#define SM_BYTES  (SM_FLOATS * 4)          // 127,744 B

__device__ __forceinline__ unsigned int smem_u32(const void* p) {
    unsigned int a;
    asm("{ .reg .u64 t; cvta.to.shared.u64 t, %1; cvt.u32.u64 %0, t; }"
        : "=r"(a) : "l"(p));
    return a;
}
__device__ __forceinline__ unsigned int mapa_rank(unsigned int laddr,
                                                  unsigned int rank) {
    unsigned int r;
    asm("mapa.shared::cluster.u32 %0, %1, %2;" : "=r"(r) : "r"(laddr), "r"(rank));
    return r;
}
__device__ __forceinline__ void st_clu(unsigned int raddr, float v) {
    asm volatile("st.shared::cluster.f32 [%0], %1;" :: "r"(raddr), "f"(v) : "memory");
}
#define CLUSTER_SYNC() do { \
    asm volatile("barrier.cluster.arrive.aligned;" ::: "memory"); \
    asm volatile("barrier.cluster.wait.aligned;" ::: "memory"); \
} while (0)

// ---------------------------------------------------------------------------
// One persistent clustered kernel: all 3 routing iterations for one batch
// per 4-CTA cluster. x-slice, probs, t, partial-s all SMEM/DSMEM resident.
// ---------------------------------------------------------------------------
__global__ void __cluster_dims__(CLU, 1, 1) __launch_bounds__(TPB, 1)
k_caps(const float* __restrict__ x, const float* __restrict__ w,
       float* __restrict__ out) {
    extern __shared__ float sm[];
    float* xs = sm + XS_OFF;
    float* ps = sm + PS_OFF;
    float* tS = sm + TS_OFF;
    float* sp = sm + SP_OFF;
    float* sx = sm + SX_OFF;

    const int b    = blockIdx.y;
    const int rank = blockIdx.x;           // == cluster ctarank (cluster spans x)
    const int t    = threadIdx.x;
    const int lane = t & 31;
    const int wp   = t >> 5;
    const int o    = rank * OPC + wp;      // this warp's owned output capsule

    // ---- load x slice [288][32] ----
    {
        const float4* src = (const float4*)&x[((size_t)b * NCAPS + rank * NPC) * ILEN];
        float4* dst = (float4*)xs;
        #pragma unroll
        for (int idx = t; idx < NPC * ILEN / 4; idx += TPB) dst[idx] = src[idx];
    }

    // W[o][lane][:] into registers (loop-invariant across iterations)
    float wrow[32];
    {
        const float4* wpp = (const float4*)&w[((size_t)o * OLEN + lane) * ILEN];
        #pragma unroll
        for (int m = 0; m < 8; m++) {
            const float4 v = wpp[m];
            wrow[m*4+0]=v.x; wrow[m*4+1]=v.y; wrow[m*4+2]=v.z; wrow[m*4+3]=v.w;
        }
    }
    __syncthreads();

    // ---- iter 0: colsum partial -> broadcast to all peers ----
    {
        float acc = 0.f;
        #pragma unroll
        for (int k = 0; k < NPW; k++)
            acc += xs[(wp + k * NWARP) * ILEN + lane];
        float* red = ps;                   // reuse ps area
        red[wp * 32 + lane] = acc;
        __syncthreads();
        if (t < 32) {
            float s = 0.f;
            #pragma unroll
            for (int k = 0; k < NWARP; k++) s += red[k * 32 + t];
            const unsigned int la = smem_u32(&sx[rank * 32 + t]);
            #pragma unroll
            for (int p = 0; p < CLU; p++) st_clu(mapa_rank(la, p), s);
        }
    }
    CLUSTER_SYNC();

    float t_acc = 0.f;   // cumulative t[o][i=lane] across iterations

    // ================= 3 iterations =================
    for (int iter = 0; iter < 3; iter++) {
        if (iter > 0) {
            // ---- phase 1: logits + softmax for my 288 n ----
            float t0[32], t1[32];
            #pragma unroll
            for (int i = 0; i < 32; i++) {
                t0[i] = tS[lane * 33 + i];
                t1[i] = tS[(lane + 32) * 33 + i];
            }
            #pragma unroll
            for (int k = 0; k < NPW; k += 2) {
                const int na = wp * NPW + k;
                const int nb = na + 1;
                float a0 = 0.f, a1 = 0.f, c0 = 0.f, c1 = 0.f;
                #pragma unroll
                for (int m = 0; m < 8; m++) {
                    const float4 xa = *(const float4*)&xs[na * ILEN + m * 4];
                    const float4 xb = *(const float4*)&xs[nb * ILEN + m * 4];
                    a0 += t0[m*4]*xa.x + t0[m*4+1]*xa.y + t0[m*4+2]*xa.z + t0[m*4+3]*xa.w;
                    a1 += t1[m*4]*xa.x + t1[m*4+1]*xa.y + t1[m*4+2]*xa.z + t1[m*4+3]*xa.w;
                    c0 += t0[m*4]*xb.x + t0[m*4+1]*xb.y + t0[m*4+2]*xb.z + t0[m*4+3]*xb.w;
                    c1 += t1[m*4]*xb.x + t1[m*4+1]*xb.y + t1[m*4+2]*xb.z + t1[m*4+3]*xb.w;
                }
                float mxa = fmaxf(a0, a1), mxb = fmaxf(c0, c1);
                #pragma unroll
                for (int off = 16; off; off >>= 1) {
                    mxa = fmaxf(mxa, __shfl_xor_sync(0xffffffffu, mxa, off));
                    mxb = fmaxf(mxb, __shfl_xor_sync(0xffffffffu, mxb, off));
                }
                const float ea0 = __expf(a0 - mxa), ea1 = __expf(a1 - mxa);
                const float eb0 = __expf(c0 - mxb), eb1 = __expf(c1 - mxb);
                float sa = ea0 + ea1, sb = eb0 + eb1;
                #pragma unroll
                for (int off = 16; off; off >>= 1) {
                    sa += __shfl_xor_sync(0xffffffffu, sa, off);
                    sb += __shfl_xor_sync(0xffffffffu, sb, off);
                }
                const float ia = 1.0f / sa, ib = 1.0f / sb;
                ps[na * OCAPS + lane]      = ea0 * ia;
                ps[na * OCAPS + lane + 32] = ea1 * ia;
                ps[nb * OCAPS + lane]      = eb0 * ib;
                ps[nb * OCAPS + lane + 32] = eb1 * ib;
            }
            __syncthreads();

            // ---- phase 2: partial s over my 288 n, warp owns 4 o ----
            const int o4 = wp * 4;
            float a0 = 0.f, a1 = 0.f, a2 = 0.f, a3 = 0.f;
            #pragma unroll 4
            for (int n = 0; n < NPC; n++) {
                const float xv = xs[n * ILEN + lane];
                const float4 p = *(const float4*)&ps[n * OCAPS + o4];
                a0 += p.x * xv; a1 += p.y * xv; a2 += p.z * xv; a3 += p.w * xv;
            }
            // deliver to owner CTA's slot [myrank]
            {
                const unsigned int owner  = (unsigned int)(o4 >> 4);
                const int          olocal = o4 & 15;
                const unsigned int la =
                    smem_u32(&sp[(rank * OPC + olocal) * 32 + lane]);
                const unsigned int ra = mapa_rank(la, owner);
                st_clu(ra,       a0);
                st_clu(ra + 128, a1);
                st_clu(ra + 256, a2);
                st_clu(ra + 384, a3);
            }
            CLUSTER_SYNC();
        }

        // ---- out/t step: warp handles its owned o ----
        float s_l;
        if (iter == 0) {
            s_l = (sx[lane] + sx[32 + lane] + sx[64 + lane] + sx[96 + lane])
                  * (1.0f / OCAPS);
        } else {
            s_l = sp[(0 * OPC + wp) * 32 + lane] + sp[(1 * OPC + wp) * 32 + lane]
                + sp[(2 * OPC + wp) * 32 + lane] + sp[(3 * OPC + wp) * 32 + lane];
        }

        float out_l = 0.f;
        #pragma unroll
        for (int i = 0; i < 32; i++)
            out_l += wrow[i] * __shfl_sync(0xffffffffu, s_l, i);

        float ss = out_l * out_l;
        #pragma unroll
        for (int off = 16; off; off >>= 1)
            ss += __shfl_xor_sync(0xffffffffu, ss, off);
        out_l *= sqrtf(ss) / (1.0f + ss);

        if (iter == 2) {
            out[((size_t)b * OCAPS + o) * OLEN + lane] = out_l;
        } else {
            // t[o][i=lane] for THIS iteration; accumulate into register t_acc
            float t_l = 0.f;
            #pragma unroll
            for (int l = 0; l < 32; l++)
                t_l += w[((size_t)o * OLEN + l) * ILEN + lane] *
                       __shfl_sync(0xffffffffu, out_l, l);
            t_acc += t_l;                          // cumulative agreement
            const unsigned int la = smem_u32(&tS[o * 33 + lane]);
            #pragma unroll
            for (int p = 0; p < CLU; p++) st_clu(mapa_rank(la, p), t_acc);
            CLUSTER_SYNC();
        }
    }
}

// ---------------------------------------------------------------------------
extern "C" void kernel_launch(void* const* d_in, const int* in_sizes, int n_in,
                              void* d_out, int out_size) {
    const float* x = (const float*)d_in[0];   // [32,1152,32]
    const float* w = (const float*)d_in[1];   // [64,32,32]
    float* out = (float*)d_out;               // [32,64,32]

    cudaFuncSetAttribute(k_caps, cudaFuncAttributeMaxDynamicSharedMemorySize,
                         SM_BYTES);
    k_caps<<<dim3(CLU, BATCH), TPB, SM_BYTES>>>(x, w, out);
}

// round 8
// speedup vs baseline: 15.7174x; 1.0008x over previous
#include <cuda_runtime.h>
#include <cuda_bf16.h>
#include <cstdint>
#include <stdint.h>
#include <math.h>

#define BATCH   32
#define NCAPS   1152
#define ILEN    32
#define OCAPS   64
#define OLEN    32
#define CLU     4                  // CTAs per cluster (one cluster per batch)
#define NPC     (NCAPS / CLU)      // 288 input caps per CTA
#define OPC     (OCAPS / CLU)      // 16 output caps per CTA
#define TPB     512
#define NWARP   16
#define NPW     (NPC / NWARP)      // 18 n per warp in phase 1

// SMEM layout (float offsets)
#define XS_OFF  0                          // [288][32]         9216
#define PS_OFF  (XS_OFF + NPC * ILEN)      // [288][64]        18432
#define TS_OFF  (PS_OFF + NPC * OCAPS)     // [64][36] padded   2304 (16B-aligned rows)
#define SP_OFF  (TS_OFF + OCAPS * 36)      // [8][16][32]       4096
#define SX_OFF  (SP_OFF + 8 * OPC * 32)    // [4][32]            128
#define SM_FLOATS (SX_OFF + CLU * 32)
#define SM_BYTES  (SM_FLOATS * 4)          // 136,704 B

__device__ __forceinline__ unsigned int smem_u32(const void* p) {
    unsigned int a;
    asm("{ .reg .u64 t; cvta.to.shared.u64 t, %1; cvt.u32.u64 %0, t; }"
        : "=r"(a) : "l"(p));
    return a;
}
__device__ __forceinline__ unsigned int mapa_rank(unsigned int laddr,
                                                  unsigned int rank) {
    unsigned int r;
    asm("mapa.shared::cluster.u32 %0, %1, %2;" : "=r"(r) : "r"(laddr), "r"(rank));
    return r;
}
__device__ __forceinline__ void st_clu(unsigned int raddr, float v) {
    asm volatile("st.shared::cluster.f32 [%0], %1;" :: "r"(raddr), "f"(v) : "memory");
}
#define CLUSTER_SYNC() do { \
    asm volatile("barrier.cluster.arrive.aligned;" ::: "memory"); \
    asm volatile("barrier.cluster.wait.aligned;" ::: "memory"); \
} while (0)

// packed fp32x2 helpers (FFMA2 path — only reachable via PTX)
__device__ __forceinline__ void ffma2(unsigned long long& d,
                                      unsigned long long a,
                                      unsigned long long b) {
    asm("fma.rn.f32x2 %0, %1, %2, %0;" : "+l"(d) : "l"(a), "l"(b));
}
__device__ __forceinline__ float2 unpack2(unsigned long long v) {
    float2 r;
    asm("mov.b64 {%0, %1}, %2;" : "=f"(r.x), "=f"(r.y) : "l"(v));
    return r;
}
__device__ __forceinline__ unsigned long long splat2(float v) {
    unsigned long long r;
    asm("mov.b64 %0, {%1, %1};" : "=l"(r) : "f"(v));
    return r;
}

// ---------------------------------------------------------------------------
// One persistent clustered kernel: all 3 routing iterations for one batch
// per 4-CTA cluster. x-slice, probs, t, partial-s all SMEM/DSMEM resident.
// ---------------------------------------------------------------------------
__global__ void __cluster_dims__(CLU, 1, 1) __launch_bounds__(TPB, 1)
k_caps(const float* __restrict__ x, const float* __restrict__ w,
       float* __restrict__ out) {
    extern __shared__ float sm[];
    float* xs = sm + XS_OFF;
    float* ps = sm + PS_OFF;
    float* tS = sm + TS_OFF;
    float* sp = sm + SP_OFF;
    float* sx = sm + SX_OFF;

    const int b    = blockIdx.y;
    const int rank = blockIdx.x;
    const int t    = threadIdx.x;
    const int lane = t & 31;
    const int wp   = t >> 5;
    const int o    = rank * OPC + wp;      // this warp's owned output capsule

    // ---- load x slice [288][32] ----
    {
        const float4* src = (const float4*)&x[((size_t)b * NCAPS + rank * NPC) * ILEN];
        float4* dst = (float4*)xs;
        #pragma unroll
        for (int idx = t; idx < NPC * ILEN / 4; idx += TPB) dst[idx] = src[idx];
    }
    __syncthreads();

    // ---- iter 0: colsum partial -> broadcast to all peers ----
    {
        float acc = 0.f;
        #pragma unroll
        for (int k = 0; k < NPW; k++)
            acc += xs[(wp + k * NWARP) * ILEN + lane];
        float* red = ps;                   // reuse ps area
        red[wp * 32 + lane] = acc;
        __syncthreads();
        if (t < 32) {
            float s = 0.f;
            #pragma unroll
            for (int k = 0; k < NWARP; k++) s += red[k * 32 + t];
            const unsigned int la = smem_u32(&sx[rank * 32 + t]);
            #pragma unroll
            for (int p = 0; p < CLU; p++) st_clu(mapa_rank(la, p), s);
        }
    }
    CLUSTER_SYNC();

    float t_acc = 0.f;   // cumulative t[o][i=lane] across iterations

    // ================= 3 iterations =================
    for (int iter = 0; iter < 3; iter++) {
        if (iter > 0) {
            // ---- phase 1: logits + softmax for my 18 n (i-packed FFMA2) ----
            unsigned long long tp0[16], tp1[16];
            {
                const ulonglong2* a = (const ulonglong2*)&tS[lane * 36];
                const ulonglong2* c = (const ulonglong2*)&tS[(lane + 32) * 36];
                #pragma unroll
                for (int m = 0; m < 8; m++) {
                    ulonglong2 v = a[m];
                    tp0[2*m] = v.x; tp0[2*m+1] = v.y;
                    v = c[m];
                    tp1[2*m] = v.x; tp1[2*m+1] = v.y;
                }
            }
            #pragma unroll
            for (int k = 0; k < NPW; k += 2) {
                const int na = wp * NPW + k;
                const int nb = na + 1;
                unsigned long long pa0 = 0, pa1 = 0, pb0 = 0, pb1 = 0;
                const ulonglong2* xa = (const ulonglong2*)&xs[na * ILEN];
                const ulonglong2* xb = (const ulonglong2*)&xs[nb * ILEN];
                #pragma unroll
                for (int m = 0; m < 8; m++) {
                    const ulonglong2 va = xa[m];
                    const ulonglong2 vb = xb[m];
                    ffma2(pa0, tp0[2*m], va.x); ffma2(pa0, tp0[2*m+1], va.y);
                    ffma2(pa1, tp1[2*m], va.x); ffma2(pa1, tp1[2*m+1], va.y);
                    ffma2(pb0, tp0[2*m], vb.x); ffma2(pb0, tp0[2*m+1], vb.y);
                    ffma2(pb1, tp1[2*m], vb.x); ffma2(pb1, tp1[2*m+1], vb.y);
                }
                const float2 ua0 = unpack2(pa0), ua1 = unpack2(pa1);
                const float2 ub0 = unpack2(pb0), ub1 = unpack2(pb1);
                const float a0 = ua0.x + ua0.y, a1 = ua1.x + ua1.y;
                const float c0 = ub0.x + ub0.y, c1 = ub1.x + ub1.y;

                float mxa = fmaxf(a0, a1), mxb = fmaxf(c0, c1);
                #pragma unroll
                for (int off = 16; off; off >>= 1) {
                    mxa = fmaxf(mxa, __shfl_xor_sync(0xffffffffu, mxa, off));
                    mxb = fmaxf(mxb, __shfl_xor_sync(0xffffffffu, mxb, off));
                }
                const float ea0 = __expf(a0 - mxa), ea1 = __expf(a1 - mxa);
                const float eb0 = __expf(c0 - mxb), eb1 = __expf(c1 - mxb);
                float sa = ea0 + ea1, sb = eb0 + eb1;
                #pragma unroll
                for (int off = 16; off; off >>= 1) {
                    sa += __shfl_xor_sync(0xffffffffu, sa, off);
                    sb += __shfl_xor_sync(0xffffffffu, sb, off);
                }
                const float ia = 1.0f / sa, ib = 1.0f / sb;
                ps[na * OCAPS + lane]      = ea0 * ia;
                ps[na * OCAPS + lane + 32] = ea1 * ia;
                ps[nb * OCAPS + lane]      = eb0 * ib;
                ps[nb * OCAPS + lane + 32] = eb1 * ib;
            }
            __syncthreads();

            // ---- phase 2: o-packed partial s; 2 n-groups x 8 warps x 8 o ----
            const int group = wp >> 3;
            const int ow    = (wp & 7) * 8;
            unsigned long long ac0 = 0, ac1 = 0, ac2 = 0, ac3 = 0;
            const int nbeg = group * (NPC / 2);
            #pragma unroll 4
            for (int n = nbeg; n < nbeg + NPC / 2; n++) {
                const float xv = xs[n * ILEN + lane];
                const unsigned long long xx = splat2(xv);
                const ulonglong2* pp = (const ulonglong2*)&ps[n * OCAPS + ow];
                const ulonglong2 p0 = pp[0];
                const ulonglong2 p1 = pp[1];
                ffma2(ac0, p0.x, xx); ffma2(ac1, p0.y, xx);
                ffma2(ac2, p1.x, xx); ffma2(ac3, p1.y, xx);
            }
            // deliver 8 o-rows to owner CTA's slot [rank*2+group]
            {
                const unsigned int owner = (unsigned int)(ow >> 4);
                const int ol   = ow & 15;            // 0 or 8
                const int slot = rank * 2 + group;
                const unsigned int la =
                    smem_u32(&sp[(slot * OPC + ol) * 32 + lane]);
                const unsigned int ra = mapa_rank(la, owner);
                const float2 u0 = unpack2(ac0), u1 = unpack2(ac1);
                const float2 u2 = unpack2(ac2), u3 = unpack2(ac3);
                st_clu(ra +   0, u0.x); st_clu(ra + 128, u0.y);
                st_clu(ra + 256, u1.x); st_clu(ra + 384, u1.y);
                st_clu(ra + 512, u2.x); st_clu(ra + 640, u2.y);
                st_clu(ra + 768, u3.x); st_clu(ra + 896, u3.y);
            }
            CLUSTER_SYNC();
        }

        // ---- out/t step: warp handles its owned o ----
        float s_l;
        if (iter == 0) {
            s_l = (sx[lane] + sx[32 + lane] + sx[64 + lane] + sx[96 + lane])
                  * (1.0f / OCAPS);
        } else {
            s_l = 0.f;
            #pragma unroll
            for (int slot = 0; slot < 8; slot++)
                s_l += sp[(slot * OPC + wp) * 32 + lane];
        }

        float wrow[32];
        {
            const float4* wpp = (const float4*)&w[((size_t)o * OLEN + lane) * ILEN];
            #pragma unroll
            for (int m = 0; m < 8; m++) {
                const float4 v = wpp[m];
                wrow[m*4+0]=v.x; wrow[m*4+1]=v.y; wrow[m*4+2]=v.z; wrow[m*4+3]=v.w;
            }
        }
        float out_l = 0.f;
        #pragma unroll
        for (int i = 0; i < 32; i++)
            out_l += wrow[i] * __shfl_sync(0xffffffffu, s_l, i);

        float ss = out_l * out_l;
        #pragma unroll
        for (int off = 16; off; off >>= 1)
            ss += __shfl_xor_sync(0xffffffffu, ss, off);
        out_l *= sqrtf(ss) / (1.0f + ss);

        if (iter == 2) {
            out[((size_t)b * OCAPS + o) * OLEN + lane] = out_l;
        } else {
            // t[o][i=lane] this iteration; accumulate cumulatively in register
            float t_l = 0.f;
            #pragma unroll
            for (int l = 0; l < 32; l++)
                t_l += w[((size_t)o * OLEN + l) * ILEN + lane] *
                       __shfl_sync(0xffffffffu, out_l, l);
            t_acc += t_l;
            const unsigned int la = smem_u32(&tS[o * 36 + lane]);
            #pragma unroll
            for (int p = 0; p < CLU; p++) st_clu(mapa_rank(la, p), t_acc);
            CLUSTER_SYNC();
        }
    }
}

// ---------------------------------------------------------------------------
extern "C" void kernel_launch(void* const* d_in, const int* in_sizes, int n_in,
                              void* d_out, int out_size) {
    const float* x = (const float*)d_in[0];   // [32,1152,32]
    const float* w = (const float*)d_in[1];   // [64,32,32]
    float* out = (float*)d_out;               // [32,64,32]

    cudaFuncSetAttribute(k_caps, cudaFuncAttributeMaxDynamicSharedMemorySize,
                         SM_BYTES);
    k_caps<<<dim3(CLU, BATCH), TPB, SM_BYTES>>>(x, w, out);
}